// round 5
// baseline (speedup 1.0000x reference)
#include <cuda_runtime.h>
#include <stdint.h>

// TwoHotEmbedding: out[b,s,:] = W[i1[b,s]] + (i1!=i2 ? W[i2[b,s]] : 0)
// i1,i2 [8,4096] int32; W [50257,512] f32; out [8,4096,512] f32.
//
// R5: warp-per-token with 256-bit (v8.b32) loads/stores — sm_103-native.
// Each lane owns two 32B chunks of the 2048B row (offsets lane*8, lane*8+256
// floats). 4 gather LDG.256 + 2 STG.256 per thread (was 8+4 at 128-bit):
// halves LSU issue + wavefront count, larger DRAM bursts. W loads keep the
// inline .L2::evict_last (legal on v8.b32 per ptxas), stores stay .cs.

static constexpr int NTOK = 8 * 4096;   // 32768 tokens
static constexpr int ROWF = 512;        // floats per row

__device__ __forceinline__ void ldg8_el(const float* p, float v[8])
{
    unsigned r0, r1, r2, r3, r4, r5, r6, r7;
    asm volatile("ld.global.nc.L2::evict_last.v8.b32 {%0,%1,%2,%3,%4,%5,%6,%7}, [%8];"
                 : "=r"(r0), "=r"(r1), "=r"(r2), "=r"(r3),
                   "=r"(r4), "=r"(r5), "=r"(r6), "=r"(r7)
                 : "l"(p));
    v[0] = __uint_as_float(r0); v[1] = __uint_as_float(r1);
    v[2] = __uint_as_float(r2); v[3] = __uint_as_float(r3);
    v[4] = __uint_as_float(r4); v[5] = __uint_as_float(r5);
    v[6] = __uint_as_float(r6); v[7] = __uint_as_float(r7);
}

__device__ __forceinline__ void stg8_cs(float* p, const float v[8])
{
    asm volatile("st.global.cs.v8.b32 [%0], {%1,%2,%3,%4,%5,%6,%7,%8};"
                 :: "l"(p),
                    "r"(__float_as_uint(v[0])), "r"(__float_as_uint(v[1])),
                    "r"(__float_as_uint(v[2])), "r"(__float_as_uint(v[3])),
                    "r"(__float_as_uint(v[4])), "r"(__float_as_uint(v[5])),
                    "r"(__float_as_uint(v[6])), "r"(__float_as_uint(v[7]))
                 : "memory");
}

__global__ void __launch_bounds__(256)
twohot_kernel(const int* __restrict__ i1,
              const int* __restrict__ i2,
              const float* __restrict__ W,
              float* __restrict__ out)
{
    int warp = blockIdx.x * (blockDim.x >> 5) + (threadIdx.x >> 5);
    int lane = threadIdx.x & 31;
    if (warp >= NTOK) return;

    int a = __ldg(i1 + warp);   // warp-uniform broadcast
    int b = __ldg(i2 + warp);

    const float* ra = W + (long long)a * ROWF + lane * 8;
    const float* rb = W + (long long)b * ROWF + lane * 8;
    float*       o  = out + (long long)warp * ROWF + lane * 8;

    // 4 independent 32B loads per thread (1024B contiguous per warp-load).
    float a0[8], a1[8], b0[8], b1[8];
    ldg8_el(ra,        a0);
    ldg8_el(ra + 256,  a1);
    ldg8_el(rb,        b0);
    ldg8_el(rb + 256,  b1);

    float m = (a != b) ? 1.0f : 0.0f;   // warp-uniform

#pragma unroll
    for (int i = 0; i < 8; i++) {
        a0[i] = fmaf(m, b0[i], a0[i]);
        a1[i] = fmaf(m, b1[i], a1[i]);
    }

    stg8_cs(o,       a0);
    stg8_cs(o + 256, a1);
}

extern "C" void kernel_launch(void* const* d_in, const int* in_sizes, int n_in,
                              void* d_out, int out_size)
{
    const int*   i1 = (const int*)d_in[0];
    const int*   i2 = (const int*)d_in[1];
    const float* W  = (const float*)d_in[2];
    float*       out = (float*)d_out;

    const int threads = 256;          // 8 warps = 8 tokens per block
    const int blocks = NTOK / 8;      // 4096 blocks
    twohot_kernel<<<blocks, threads>>>(i1, i2, W, out);
}